// round 3
// baseline (speedup 1.0000x reference)
#include <cuda_runtime.h>
#include <cstdint>

#define BSZ 8
#define SEQ 1024
#define DIM 512
#define NHEAD 8
#define HDIM 64
#define NTOK (BSZ*SEQ)                 // 8192
#define NELEM ((size_t)NTOK*DIM)       // 4194304

// Intermediate scratch (static device globals; no allocations).
__device__ float g_q[NELEM];
__device__ float g_k[NELEM];
__device__ float g_v[NELEM];
__device__ float g_att[NELEM];
__device__ float g_ln0[NELEM];
__device__ float g_mid[NELEM];

// ---------------------------------------------------------------------------
// cp.async helpers
// ---------------------------------------------------------------------------
__device__ __forceinline__ void cp16(void* smem_dst, const void* gmem_src) {
    unsigned int s = (unsigned int)__cvta_generic_to_shared(smem_dst);
    asm volatile("cp.async.cg.shared.global [%0], [%1], 16;"
                 :: "r"(s), "l"(gmem_src) : "memory");
}
__device__ __forceinline__ void cp_commit() {
    asm volatile("cp.async.commit_group;" ::: "memory");
}
__device__ __forceinline__ void cp_wait0() {
    asm volatile("cp.async.wait_group 0;" ::: "memory");
}
__device__ __forceinline__ void cp_wait1() {
    asm volatile("cp.async.wait_group 1;" ::: "memory");
}

// ---------------------------------------------------------------------------
// 128x128x16 fp32 tiled GEMM, 2-stage pipelined (A reg-staged, B cp.async).
// C[M,512] = A[M,512] @ W[512,512].
// MODE 0: C = acc + bias
// MODE 1: C = resid + relu(acc + bias)
// ---------------------------------------------------------------------------
template <int MODE>
__device__ __forceinline__ void gemm_body(const float* __restrict__ A,
                                          const float* __restrict__ W,
                                          const float* __restrict__ bias,
                                          const float* __restrict__ resid,
                                          float* __restrict__ C)
{
    const int K = DIM, N = DIM;
    __shared__ float As[2][16][128];
    __shared__ float Bs[2][16][128];

    const int row0 = blockIdx.y * 128;
    const int col0 = blockIdx.x * 128;
    const int tid  = threadIdx.x;          // 0..255
    const int tx   = tid & 15;
    const int ty   = tid >> 4;

    // A load indices (2 float4 per thread, transposed store)
    const int rA0  = tid >> 2;             // 0..63
    const int kqA0 = (tid & 3) * 4;
    const int rA1  = rA0 + 64;
    const int kqA1 = kqA0;
    // B cp.async indices (2 x 16B per thread)
    const int krB0 = tid >> 5;             // 0..7
    const int krB1 = krB0 + 8;
    const int cq   = tid & 31;

    float c[8][8];
#pragma unroll
    for (int i = 0; i < 8; i++)
#pragma unroll
        for (int j = 0; j < 8; j++) c[i][j] = 0.f;

    float4 a0, a1;

    // ---- prologue: stage 0 ----
    a0 = *(const float4*)(A + (size_t)(row0 + rA0) * K + kqA0);
    a1 = *(const float4*)(A + (size_t)(row0 + rA1) * K + kqA1);
    As[0][kqA0 + 0][rA0] = a0.x;
    As[0][kqA0 + 1][rA0] = a0.y;
    As[0][kqA0 + 2][rA0] = a0.z;
    As[0][kqA0 + 3][rA0] = a0.w;
    As[0][kqA1 + 0][rA1] = a1.x;
    As[0][kqA1 + 1][rA1] = a1.y;
    As[0][kqA1 + 2][rA1] = a1.z;
    As[0][kqA1 + 3][rA1] = a1.w;
    cp16(&Bs[0][krB0][cq * 4], W + (size_t)krB0 * N + col0 + cq * 4);
    cp16(&Bs[0][krB1][cq * 4], W + (size_t)krB1 * N + col0 + cq * 4);
    cp_commit();
    cp_wait0();
    __syncthreads();

    const int NIT = K / 16;   // 32
    for (int it = 0; it < NIT; ++it) {
        const int buf  = it & 1;
        const int nbuf = buf ^ 1;
        const int kn   = (it + 1) * 16;

        if (it < NIT - 1) {
            a0 = *(const float4*)(A + (size_t)(row0 + rA0) * K + kn + kqA0);
            a1 = *(const float4*)(A + (size_t)(row0 + rA1) * K + kn + kqA1);
            cp16(&Bs[nbuf][krB0][cq * 4], W + (size_t)(kn + krB0) * N + col0 + cq * 4);
            cp16(&Bs[nbuf][krB1][cq * 4], W + (size_t)(kn + krB1) * N + col0 + cq * 4);
            cp_commit();
        }

#pragma unroll
        for (int k = 0; k < 16; k++) {
            float4 av0 = *(((const float4*)&As[buf][k][0]) + ty);
            float4 av1 = *(((const float4*)&As[buf][k][0]) + ty + 16);
            float4 bv0 = *(((const float4*)&Bs[buf][k][0]) + tx);
            float4 bv1 = *(((const float4*)&Bs[buf][k][0]) + tx + 16);
            float av[8] = {av0.x, av0.y, av0.z, av0.w, av1.x, av1.y, av1.z, av1.w};
            float bv[8] = {bv0.x, bv0.y, bv0.z, bv0.w, bv1.x, bv1.y, bv1.z, bv1.w};
#pragma unroll
            for (int i = 0; i < 8; i++)
#pragma unroll
                for (int j = 0; j < 8; j++) c[i][j] += av[i] * bv[j];
        }

        if (it < NIT - 1) {
            As[nbuf][kqA0 + 0][rA0] = a0.x;
            As[nbuf][kqA0 + 1][rA0] = a0.y;
            As[nbuf][kqA0 + 2][rA0] = a0.z;
            As[nbuf][kqA0 + 3][rA0] = a0.w;
            As[nbuf][kqA1 + 0][rA1] = a1.x;
            As[nbuf][kqA1 + 1][rA1] = a1.y;
            As[nbuf][kqA1 + 2][rA1] = a1.z;
            As[nbuf][kqA1 + 3][rA1] = a1.w;
            cp_wait0();
        }
        __syncthreads();
    }

    // Epilogue
#pragma unroll
    for (int i = 0; i < 8; i++) {
        int grow = row0 + ((i < 4) ? (ty * 4 + i) : (ty * 4 + 64 + i - 4));
#pragma unroll
        for (int jh = 0; jh < 2; jh++) {
            int gcol = col0 + tx * 4 + jh * 64;
            float4 o;
            o.x = c[i][jh * 4 + 0] + bias[gcol + 0];
            o.y = c[i][jh * 4 + 1] + bias[gcol + 1];
            o.z = c[i][jh * 4 + 2] + bias[gcol + 2];
            o.w = c[i][jh * 4 + 3] + bias[gcol + 3];
            size_t gi = (size_t)grow * N + gcol;
            if (MODE == 1) {
                float4 r = *(const float4*)(resid + gi);
                o.x = r.x + fmaxf(o.x, 0.f);
                o.y = r.y + fmaxf(o.y, 0.f);
                o.z = r.z + fmaxf(o.z, 0.f);
                o.w = r.w + fmaxf(o.w, 0.f);
            }
            *(float4*)(C + gi) = o;
        }
    }
}

__global__ __launch_bounds__(256)
void qkv_gemm(const float* __restrict__ queries, const float* __restrict__ keys,
              const float* __restrict__ Wq, const float* __restrict__ bq,
              const float* __restrict__ Wk, const float* __restrict__ bk,
              const float* __restrict__ Wv, const float* __restrict__ bv)
{
    const float* A; const float* W; const float* bias; float* C;
    if (blockIdx.z == 0)      { A = queries; W = Wq; bias = bq; C = g_q; }
    else if (blockIdx.z == 1) { A = keys;    W = Wk; bias = bk; C = g_k; }
    else                      { A = keys;    W = Wv; bias = bv; C = g_v; }
    gemm_body<0>(A, W, bias, nullptr, C);
}

__global__ __launch_bounds__(256)
void o_gemm(const float* __restrict__ Wo, const float* __restrict__ bo)
{
    gemm_body<1>(g_ln0, Wo, bo, g_ln0, g_mid);
}

// ---------------------------------------------------------------------------
// Flash attention: one thread per (b,h,sq) row, d=64 in registers.
// 32-key tiles, 2-stage cp.async double buffering of K/V/pk.
// o = qh + softmax(mask(qh kh^T / sqrt(512))) @ vh
// ---------------------------------------------------------------------------
#define TK 32
#define NT (SEQ / TK)   // 32

__global__ __launch_bounds__(128, 2)
void attn_kernel(const float* __restrict__ pres_q, const float* __restrict__ pres_k)
{
    const int bh = blockIdx.y;            // 0..63
    const int b  = bh >> 3;
    const int h  = bh & 7;
    const int sq = blockIdx.x * 128 + threadIdx.x;
    const int tid = threadIdx.x;

    __shared__ float Ks[2][TK * 64];
    __shared__ float Vs[2][TK * 64];
    __shared__ float pks[2][TK];

    const float* qrow = g_q + ((size_t)b * SEQ + sq) * DIM + h * HDIM;
    float4 qv[16];
#pragma unroll
    for (int i = 0; i < 16; i++) qv[i] = ((const float4*)qrow)[i];

    const float INFC  = 1e38f;
    const float rs    = 0.04419417382415922f;   // 1/sqrt(512)
    const float presq = pres_q[b * SEQ + sq];
    const float aq = presq * rs;
    const float cq = (1.f - presq) * INFC;

    float4 acc[16];
#pragma unroll
    for (int i = 0; i < 16; i++) acc[i] = make_float4(0.f, 0.f, 0.f, 0.f);
    float m = -1e38f, l = 0.f;

    const float* kbase = g_k + ((size_t)b * SEQ) * DIM + h * HDIM;
    const float* vbase = g_v + ((size_t)b * SEQ) * DIM + h * HDIM;
    const float* pkb   = pres_k + b * SEQ;

    // tile issue: K/V tiles 32 rows x 64 floats each; pk 32 floats
    auto issue_tile = [&](int t, int buf) {
        int k0 = t * TK;
#pragma unroll
        for (int i = 0; i < 4; i++) {
            int f  = tid + 128 * i;           // 0..511
            int j  = f >> 4;                  // 0..31
            int c4 = (f & 15) * 4;            // 0..60
            size_t go = (size_t)(k0 + j) * DIM + c4;
            cp16(&Ks[buf][j * 64 + c4], kbase + go);
            cp16(&Vs[buf][j * 64 + c4], vbase + go);
        }
        if (tid < 8) cp16(&pks[buf][tid * 4], pkb + k0 + tid * 4);
        cp_commit();
    };

    issue_tile(0, 0);
    issue_tile(1, 1);

    for (int t = 0; t < NT; ++t) {
        const int buf = t & 1;
        if (t == NT - 1) cp_wait0(); else cp_wait1();
        __syncthreads();

        // --- logits for 32 keys ---
        float s[TK];
#pragma unroll
        for (int j = 0; j < TK; j++) {
            const float4* kr = (const float4*)&Ks[buf][j * 64];
            float sum = 0.f;
#pragma unroll
            for (int i = 0; i < 16; i++) {
                float4 kv = kr[i];
                sum += qv[i].x * kv.x + qv[i].y * kv.y + qv[i].z * kv.z + qv[i].w * kv.w;
            }
            float l1  = aq * sum - cq;                    // == presq*(sum*rs) - (1-presq)*INF
            float pkj = pks[buf][j];
            s[j] = pkj * l1 - (1.f - pkj) * INFC;
        }

        // --- streaming softmax update ---
        float tm = s[0];
#pragma unroll
        for (int j = 1; j < TK; j++) tm = fmaxf(tm, s[j]);
        float mnew = fmaxf(m, tm);
        float fac  = __expf(m - mnew);
        m = mnew;
        l *= fac;
#pragma unroll
        for (int i = 0; i < 16; i++) {
            acc[i].x *= fac; acc[i].y *= fac; acc[i].z *= fac; acc[i].w *= fac;
        }
#pragma unroll
        for (int j = 0; j < TK; j++) {
            float p = __expf(s[j] - m);
            l += p;
            const float4* vr = (const float4*)&Vs[buf][j * 64];
#pragma unroll
            for (int i = 0; i < 16; i++) {
                float4 vvv = vr[i];
                acc[i].x += p * vvv.x;
                acc[i].y += p * vvv.y;
                acc[i].z += p * vvv.z;
                acc[i].w += p * vvv.w;
            }
        }

        __syncthreads();                 // all readers done before reuse of buf
        if (t + 2 < NT) issue_tile(t + 2, buf);
    }

    float inv = 1.f / l;
    float* orow = g_att + ((size_t)b * SEQ + sq) * DIM + h * HDIM;
#pragma unroll
    for (int i = 0; i < 16; i++) {
        float4 o;
        o.x = qv[i].x + acc[i].x * inv;
        o.y = qv[i].y + acc[i].y * inv;
        o.z = qv[i].z + acc[i].z * inv;
        o.w = qv[i].w + acc[i].w * inv;
        ((float4*)orow)[i] = o;
    }
}

// ---------------------------------------------------------------------------
// LayerNorm over last dim (512). One block per row, 128 threads.
// ---------------------------------------------------------------------------
__device__ __forceinline__ void ln_body(const float* __restrict__ in,
                                        float* __restrict__ out,
                                        const float* __restrict__ g,
                                        const float* __restrict__ b)
{
    const int row = blockIdx.x;
    const int tid = threadIdx.x;
    const float* x = in + (size_t)row * DIM;

    float v[4];
#pragma unroll
    for (int i = 0; i < 4; i++) v[i] = x[tid + i * 128];

    float s = v[0] + v[1] + v[2] + v[3];
#pragma unroll
    for (int o = 16; o > 0; o >>= 1) s += __shfl_xor_sync(0xffffffffu, s, o);
    __shared__ float red1[4];
    __shared__ float red2[4];
    int wid = tid >> 5;
    if ((tid & 31) == 0) red1[wid] = s;
    __syncthreads();
    float mu = (red1[0] + red1[1] + red1[2] + red1[3]) * (1.f / DIM);

    float q = 0.f;
#pragma unroll
    for (int i = 0; i < 4; i++) { float d = v[i] - mu; q += d * d; }
#pragma unroll
    for (int o = 16; o > 0; o >>= 1) q += __shfl_xor_sync(0xffffffffu, q, o);
    if ((tid & 31) == 0) red2[wid] = q;
    __syncthreads();
    float var  = (red2[0] + red2[1] + red2[2] + red2[3]) * (1.f / DIM);
    float rstd = rsqrtf(var + 1e-5f);

#pragma unroll
    for (int i = 0; i < 4; i++) {
        int c = tid + i * 128;
        out[(size_t)row * DIM + c] = (v[i] - mu) * rstd * g[c] + b[c];
    }
}

__global__ __launch_bounds__(128)
void ln0_kernel(const float* __restrict__ g0, const float* __restrict__ b0)
{
    ln_body(g_att, g_ln0, g0, b0);
}

__global__ __launch_bounds__(128)
void ln1_kernel(const float* __restrict__ g1, const float* __restrict__ b1,
                float* __restrict__ out)
{
    ln_body(g_mid, out, g1, b1);
}

// ---------------------------------------------------------------------------
extern "C" void kernel_launch(void* const* d_in, const int* in_sizes, int n_in,
                              void* d_out, int out_size)
{
    const float* queries = (const float*)d_in[0];
    const float* keys    = (const float*)d_in[1];
    const float* pq      = (const float*)d_in[2];
    const float* pk      = (const float*)d_in[3];

    int base = 4;
    if (n_in >= 5 && in_sizes[4] == 1) base = 5;

    const float* Wq = (const float*)d_in[base + 0];
    const float* bq = (const float*)d_in[base + 1];
    const float* Wk = (const float*)d_in[base + 2];
    const float* bk = (const float*)d_in[base + 3];
    const float* Wv = (const float*)d_in[base + 4];
    const float* bv = (const float*)d_in[base + 5];
    const float* Wo = (const float*)d_in[base + 6];
    const float* bo = (const float*)d_in[base + 7];
    const float* g0 = (const float*)d_in[base + 8];
    const float* b0 = (const float*)d_in[base + 9];
    const float* g1 = (const float*)d_in[base + 10];
    const float* b1 = (const float*)d_in[base + 11];
    float* out = (float*)d_out;

    qkv_gemm<<<dim3(DIM / 128, NTOK / 128, 3), 256>>>(queries, keys,
                                                      Wq, bq, Wk, bk, Wv, bv);
    attn_kernel<<<dim3(SEQ / 128, BSZ * NHEAD), 128>>>(pq, pk);
    ln0_kernel<<<NTOK, 128>>>(g0, b0);
    o_gemm<<<dim3(DIM / 128, NTOK / 128), 256>>>(Wo, bo);
    ln1_kernel<<<NTOK, 128>>>(g1, b1, out);
}

// round 4
// speedup vs baseline: 1.2565x; 1.2565x over previous
#include <cuda_runtime.h>
#include <cstdint>

#define BSZ 8
#define SEQ 1024
#define DIM 512
#define NHEAD 8
#define HDIM 64
#define NTOK (BSZ*SEQ)                 // 8192
#define NELEM ((size_t)NTOK*DIM)       // 4194304

// Intermediate scratch (static device globals; no allocations).
__device__ float g_q[NELEM];
__device__ float g_k[NELEM];
__device__ float g_v[NELEM];
__device__ float g_att[NELEM];
__device__ float g_ln0[NELEM];
__device__ float g_mid[NELEM];

// ---------------------------------------------------------------------------
// packed f32x2 helpers (Blackwell FFMA2 path — PTX only, ptxas never emits it)
// ---------------------------------------------------------------------------
typedef unsigned long long u64;

__device__ __forceinline__ u64 pack2(float lo, float hi) {
    u64 r;
    asm("mov.b64 %0, {%1, %2};" : "=l"(r) : "f"(lo), "f"(hi));
    return r;
}
__device__ __forceinline__ u64 dup2(float v) {
    u64 r;
    asm("mov.b64 %0, {%1, %1};" : "=l"(r) : "f"(v));
    return r;
}
__device__ __forceinline__ void unpack2(u64 p, float& lo, float& hi) {
    asm("mov.b64 {%0, %1}, %2;" : "=f"(lo), "=f"(hi) : "l"(p));
}
__device__ __forceinline__ u64 fma2(u64 a, u64 b, u64 c) {
    u64 d;
    asm("fma.rn.f32x2 %0, %1, %2, %3;" : "=l"(d) : "l"(a), "l"(b), "l"(c));
    return d;
}
__device__ __forceinline__ u64 mul2(u64 a, u64 b) {
    u64 d;
    asm("mul.rn.f32x2 %0, %1, %2;" : "=l"(d) : "l"(a), "l"(b));
    return d;
}
__device__ __forceinline__ u64 add2(u64 a, u64 b) {
    u64 d;
    asm("add.rn.f32x2 %0, %1, %2;" : "=l"(d) : "l"(a), "l"(b));
    return d;
}

// ---------------------------------------------------------------------------
// cp.async helpers
// ---------------------------------------------------------------------------
__device__ __forceinline__ void cp16(void* smem_dst, const void* gmem_src) {
    unsigned int s = (unsigned int)__cvta_generic_to_shared(smem_dst);
    asm volatile("cp.async.cg.shared.global [%0], [%1], 16;"
                 :: "r"(s), "l"(gmem_src) : "memory");
}
__device__ __forceinline__ void cp_commit() {
    asm volatile("cp.async.commit_group;" ::: "memory");
}
__device__ __forceinline__ void cp_wait0() {
    asm volatile("cp.async.wait_group 0;" ::: "memory");
}
__device__ __forceinline__ void cp_wait1() {
    asm volatile("cp.async.wait_group 1;" ::: "memory");
}

// ---------------------------------------------------------------------------
// 128x128x16 fp32 tiled GEMM, 2-stage pipelined, FFMA2 microkernel.
// C[M,512] = A[M,512] @ W[512,512].
// MODE 0: C = acc + bias
// MODE 1: C = resid + relu(acc + bias)
// ---------------------------------------------------------------------------
template <int MODE>
__device__ __forceinline__ void gemm_body(const float* __restrict__ A,
                                          const float* __restrict__ W,
                                          const float* __restrict__ bias,
                                          const float* __restrict__ resid,
                                          float* __restrict__ C)
{
    const int K = DIM, N = DIM;
    __shared__ float As[2][16][128];
    __shared__ float Bs[2][16][128];

    const int row0 = blockIdx.y * 128;
    const int col0 = blockIdx.x * 128;
    const int tid  = threadIdx.x;          // 0..255
    const int tx   = tid & 15;
    const int ty   = tid >> 4;

    const int rA0  = tid >> 2;             // 0..63
    const int kqA0 = (tid & 3) * 4;
    const int rA1  = rA0 + 64;
    const int krB0 = tid >> 5;             // 0..7
    const int krB1 = krB0 + 8;
    const int cq   = tid & 31;

    // accumulators: 8 rows x 4 column-pairs (8 cols)
    u64 c2[8][4];
#pragma unroll
    for (int i = 0; i < 8; i++)
#pragma unroll
        for (int j = 0; j < 4; j++) c2[i][j] = 0ULL;

    float4 a0, a1;

    // ---- prologue: stage 0 ----
    a0 = *(const float4*)(A + (size_t)(row0 + rA0) * K + kqA0);
    a1 = *(const float4*)(A + (size_t)(row0 + rA1) * K + kqA0);
    As[0][kqA0 + 0][rA0] = a0.x;
    As[0][kqA0 + 1][rA0] = a0.y;
    As[0][kqA0 + 2][rA0] = a0.z;
    As[0][kqA0 + 3][rA0] = a0.w;
    As[0][kqA0 + 0][rA1] = a1.x;
    As[0][kqA0 + 1][rA1] = a1.y;
    As[0][kqA0 + 2][rA1] = a1.z;
    As[0][kqA0 + 3][rA1] = a1.w;
    cp16(&Bs[0][krB0][cq * 4], W + (size_t)krB0 * N + col0 + cq * 4);
    cp16(&Bs[0][krB1][cq * 4], W + (size_t)krB1 * N + col0 + cq * 4);
    cp_commit();
    cp_wait0();
    __syncthreads();

    const int NIT = K / 16;   // 32
    for (int it = 0; it < NIT; ++it) {
        const int buf  = it & 1;
        const int nbuf = buf ^ 1;
        const int kn   = (it + 1) * 16;

        if (it < NIT - 1) {
            a0 = *(const float4*)(A + (size_t)(row0 + rA0) * K + kn + kqA0);
            a1 = *(const float4*)(A + (size_t)(row0 + rA1) * K + kn + kqA0);
            cp16(&Bs[nbuf][krB0][cq * 4], W + (size_t)(kn + krB0) * N + col0 + cq * 4);
            cp16(&Bs[nbuf][krB1][cq * 4], W + (size_t)(kn + krB1) * N + col0 + cq * 4);
            cp_commit();
        }

#pragma unroll
        for (int k = 0; k < 16; k++) {
            float4 av0 = *(((const float4*)&As[buf][k][0]) + ty);
            float4 av1 = *(((const float4*)&As[buf][k][0]) + ty + 16);
            const ulonglong2* brow = (const ulonglong2*)&Bs[buf][k][0];
            ulonglong2 b01 = brow[tx];        // cols 4tx..4tx+3
            ulonglong2 b23 = brow[tx + 16];   // cols 64+4tx..64+4tx+3
            u64 bp[4] = {b01.x, b01.y, b23.x, b23.y};
            u64 ad[8];
            ad[0] = dup2(av0.x); ad[1] = dup2(av0.y);
            ad[2] = dup2(av0.z); ad[3] = dup2(av0.w);
            ad[4] = dup2(av1.x); ad[5] = dup2(av1.y);
            ad[6] = dup2(av1.z); ad[7] = dup2(av1.w);
#pragma unroll
            for (int i = 0; i < 8; i++)
#pragma unroll
                for (int j = 0; j < 4; j++)
                    c2[i][j] = fma2(ad[i], bp[j], c2[i][j]);
        }

        if (it < NIT - 1) {
            As[nbuf][kqA0 + 0][rA0] = a0.x;
            As[nbuf][kqA0 + 1][rA0] = a0.y;
            As[nbuf][kqA0 + 2][rA0] = a0.z;
            As[nbuf][kqA0 + 3][rA0] = a0.w;
            As[nbuf][kqA0 + 0][rA1] = a1.x;
            As[nbuf][kqA0 + 1][rA1] = a1.y;
            As[nbuf][kqA0 + 2][rA1] = a1.z;
            As[nbuf][kqA0 + 3][rA1] = a1.w;
            cp_wait0();
        }
        __syncthreads();
    }

    // Epilogue
#pragma unroll
    for (int i = 0; i < 8; i++) {
        int grow = row0 + ((i < 4) ? (ty * 4 + i) : (ty * 4 + 64 + i - 4));
        float cf[8];
        unpack2(c2[i][0], cf[0], cf[1]);
        unpack2(c2[i][1], cf[2], cf[3]);
        unpack2(c2[i][2], cf[4], cf[5]);
        unpack2(c2[i][3], cf[6], cf[7]);
#pragma unroll
        for (int jh = 0; jh < 2; jh++) {
            int gcol = col0 + tx * 4 + jh * 64;
            float4 o;
            o.x = cf[jh * 4 + 0] + bias[gcol + 0];
            o.y = cf[jh * 4 + 1] + bias[gcol + 1];
            o.z = cf[jh * 4 + 2] + bias[gcol + 2];
            o.w = cf[jh * 4 + 3] + bias[gcol + 3];
            size_t gi = (size_t)grow * N + gcol;
            if (MODE == 1) {
                float4 r = *(const float4*)(resid + gi);
                o.x = r.x + fmaxf(o.x, 0.f);
                o.y = r.y + fmaxf(o.y, 0.f);
                o.z = r.z + fmaxf(o.z, 0.f);
                o.w = r.w + fmaxf(o.w, 0.f);
            }
            *(float4*)(C + gi) = o;
        }
    }
}

__global__ __launch_bounds__(256)
void qkv_gemm(const float* __restrict__ queries, const float* __restrict__ keys,
              const float* __restrict__ Wq, const float* __restrict__ bq,
              const float* __restrict__ Wk, const float* __restrict__ bk,
              const float* __restrict__ Wv, const float* __restrict__ bv)
{
    const float* A; const float* W; const float* bias; float* C;
    if (blockIdx.z == 0)      { A = queries; W = Wq; bias = bq; C = g_q; }
    else if (blockIdx.z == 1) { A = keys;    W = Wk; bias = bk; C = g_k; }
    else                      { A = keys;    W = Wv; bias = bv; C = g_v; }
    gemm_body<0>(A, W, bias, nullptr, C);
}

__global__ __launch_bounds__(256)
void o_gemm(const float* __restrict__ Wo, const float* __restrict__ bo)
{
    gemm_body<1>(g_ln0, Wo, bo, g_ln0, g_mid);
}

// ---------------------------------------------------------------------------
// Flash attention: one thread per (b,h,sq) row, d=64 in registers (packed).
// 32-key tiles, 2-stage cp.async double buffering, FFMA2 inner loops.
// o = qh + softmax(mask(qh kh^T / sqrt(512))) @ vh
// ---------------------------------------------------------------------------
#define TK 32
#define NT (SEQ / TK)   // 32

__global__ __launch_bounds__(128, 2)
void attn_kernel(const float* __restrict__ pres_q, const float* __restrict__ pres_k)
{
    const int bh = blockIdx.y;            // 0..63
    const int b  = bh >> 3;
    const int h  = bh & 7;
    const int sq = blockIdx.x * 128 + threadIdx.x;
    const int tid = threadIdx.x;

    __shared__ float Ks[2][TK * 64];
    __shared__ float Vs[2][TK * 64];
    __shared__ float pks[2][TK];

    // q row: 64 floats = 32 packed pairs
    const float* qrow = g_q + ((size_t)b * SEQ + sq) * DIM + h * HDIM;
    u64 q2[32];
#pragma unroll
    for (int i = 0; i < 16; i++) {
        ulonglong2 t = ((const ulonglong2*)qrow)[i];
        q2[2 * i]     = t.x;
        q2[2 * i + 1] = t.y;
    }

    const float INFC  = 1e38f;
    const float rs    = 0.04419417382415922f;   // 1/sqrt(512)
    const float presq = pres_q[b * SEQ + sq];
    const float aq = presq * rs;
    const float cqv = (1.f - presq) * INFC;

    u64 acc2[32];
#pragma unroll
    for (int i = 0; i < 32; i++) acc2[i] = 0ULL;
    float m = -1e38f, l = 0.f;

    const float* kbase = g_k + ((size_t)b * SEQ) * DIM + h * HDIM;
    const float* vbase = g_v + ((size_t)b * SEQ) * DIM + h * HDIM;
    const float* pkb   = pres_k + b * SEQ;

    auto issue_tile = [&](int t, int buf) {
        int k0 = t * TK;
#pragma unroll
        for (int i = 0; i < 4; i++) {
            int f  = tid + 128 * i;           // 0..511
            int j  = f >> 4;                  // 0..31
            int c4 = (f & 15) * 4;            // 0..60
            size_t go = (size_t)(k0 + j) * DIM + c4;
            cp16(&Ks[buf][j * 64 + c4], kbase + go);
            cp16(&Vs[buf][j * 64 + c4], vbase + go);
        }
        if (tid < 8) cp16(&pks[buf][tid * 4], pkb + k0 + tid * 4);
        cp_commit();
    };

    issue_tile(0, 0);
    issue_tile(1, 1);

    for (int t = 0; t < NT; ++t) {
        const int buf = t & 1;
        if (t == NT - 1) cp_wait0(); else cp_wait1();
        __syncthreads();

        // --- logits for 32 keys (32 FFMA2 each, two chains) ---
        float s[TK];
#pragma unroll
        for (int j = 0; j < TK; j++) {
            const ulonglong2* kr = (const ulonglong2*)&Ks[buf][j * 64];
            u64 sa = 0ULL, sb = 0ULL;
#pragma unroll
            for (int i = 0; i < 16; i++) {
                ulonglong2 kk = kr[i];
                sa = fma2(q2[2 * i],     kk.x, sa);
                sb = fma2(q2[2 * i + 1], kk.y, sb);
            }
            float lo, hi;
            unpack2(add2(sa, sb), lo, hi);
            float sum = lo + hi;
            float l1  = aq * sum - cqv;
            float pkj = pks[buf][j];
            s[j] = pkj * l1 - (1.f - pkj) * INFC;
        }

        // --- streaming softmax update ---
        float tm = s[0];
#pragma unroll
        for (int j = 1; j < TK; j++) tm = fmaxf(tm, s[j]);
        float mnew = fmaxf(m, tm);
        float fac  = __expf(m - mnew);
        m = mnew;
        l *= fac;
        u64 facd = dup2(fac);
#pragma unroll
        for (int i = 0; i < 32; i++) acc2[i] = mul2(acc2[i], facd);

#pragma unroll
        for (int j = 0; j < TK; j++) {
            float p = __expf(s[j] - m);
            l += p;
            u64 pd = dup2(p);
            const ulonglong2* vr = (const ulonglong2*)&Vs[buf][j * 64];
#pragma unroll
            for (int i = 0; i < 16; i++) {
                ulonglong2 vv = vr[i];
                acc2[2 * i]     = fma2(pd, vv.x, acc2[2 * i]);
                acc2[2 * i + 1] = fma2(pd, vv.y, acc2[2 * i + 1]);
            }
        }

        __syncthreads();                 // all readers done before buf reuse
        if (t + 2 < NT) issue_tile(t + 2, buf);
    }

    float inv = 1.f / l;
    float* orow = g_att + ((size_t)b * SEQ + sq) * DIM + h * HDIM;
#pragma unroll
    for (int i = 0; i < 16; i++) {
        float a0, a1, a2, a3, q0, q1, q2f, q3;
        unpack2(acc2[2 * i],     a0, a1);
        unpack2(acc2[2 * i + 1], a2, a3);
        unpack2(q2[2 * i],       q0, q1);
        unpack2(q2[2 * i + 1],   q2f, q3);
        float4 o;
        o.x = q0  + a0 * inv;
        o.y = q1  + a1 * inv;
        o.z = q2f + a2 * inv;
        o.w = q3  + a3 * inv;
        ((float4*)orow)[i] = o;
    }
}

// ---------------------------------------------------------------------------
// LayerNorm over last dim (512). One block per row, 128 threads.
// ---------------------------------------------------------------------------
__device__ __forceinline__ void ln_body(const float* __restrict__ in,
                                        float* __restrict__ out,
                                        const float* __restrict__ g,
                                        const float* __restrict__ b)
{
    const int row = blockIdx.x;
    const int tid = threadIdx.x;
    const float* x = in + (size_t)row * DIM;

    float v[4];
#pragma unroll
    for (int i = 0; i < 4; i++) v[i] = x[tid + i * 128];

    float s = v[0] + v[1] + v[2] + v[3];
#pragma unroll
    for (int o = 16; o > 0; o >>= 1) s += __shfl_xor_sync(0xffffffffu, s, o);
    __shared__ float red1[4];
    __shared__ float red2[4];
    int wid = tid >> 5;
    if ((tid & 31) == 0) red1[wid] = s;
    __syncthreads();
    float mu = (red1[0] + red1[1] + red1[2] + red1[3]) * (1.f / DIM);

    float q = 0.f;
#pragma unroll
    for (int i = 0; i < 4; i++) { float d = v[i] - mu; q += d * d; }
#pragma unroll
    for (int o = 16; o > 0; o >>= 1) q += __shfl_xor_sync(0xffffffffu, q, o);
    if ((tid & 31) == 0) red2[wid] = q;
    __syncthreads();
    float var  = (red2[0] + red2[1] + red2[2] + red2[3]) * (1.f / DIM);
    float rstd = rsqrtf(var + 1e-5f);

#pragma unroll
    for (int i = 0; i < 4; i++) {
        int c = tid + i * 128;
        out[(size_t)row * DIM + c] = (v[i] - mu) * rstd * g[c] + b[c];
    }
}

__global__ __launch_bounds__(128)
void ln0_kernel(const float* __restrict__ g0, const float* __restrict__ b0)
{
    ln_body(g_att, g_ln0, g0, b0);
}

__global__ __launch_bounds__(128)
void ln1_kernel(const float* __restrict__ g1, const float* __restrict__ b1,
                float* __restrict__ out)
{
    ln_body(g_mid, out, g1, b1);
}

// ---------------------------------------------------------------------------
extern "C" void kernel_launch(void* const* d_in, const int* in_sizes, int n_in,
                              void* d_out, int out_size)
{
    const float* queries = (const float*)d_in[0];
    const float* keys    = (const float*)d_in[1];
    const float* pq      = (const float*)d_in[2];
    const float* pk      = (const float*)d_in[3];

    int base = 4;
    if (n_in >= 5 && in_sizes[4] == 1) base = 5;

    const float* Wq = (const float*)d_in[base + 0];
    const float* bq = (const float*)d_in[base + 1];
    const float* Wk = (const float*)d_in[base + 2];
    const float* bk = (const float*)d_in[base + 3];
    const float* Wv = (const float*)d_in[base + 4];
    const float* bv = (const float*)d_in[base + 5];
    const float* Wo = (const float*)d_in[base + 6];
    const float* bo = (const float*)d_in[base + 7];
    const float* g0 = (const float*)d_in[base + 8];
    const float* b0 = (const float*)d_in[base + 9];
    const float* g1 = (const float*)d_in[base + 10];
    const float* b1 = (const float*)d_in[base + 11];
    float* out = (float*)d_out;

    qkv_gemm<<<dim3(DIM / 128, NTOK / 128, 3), 256>>>(queries, keys,
                                                      Wq, bq, Wk, bk, Wv, bv);
    attn_kernel<<<dim3(SEQ / 128, BSZ * NHEAD), 128>>>(pq, pk);
    ln0_kernel<<<NTOK, 128>>>(g0, b0);
    o_gemm<<<dim3(DIM / 128, NTOK / 128), 256>>>(Wo, bo);
    ln1_kernel<<<NTOK, 128>>>(g1, b1, out);
}